// round 5
// baseline (speedup 1.0000x reference)
#include <cuda_runtime.h>
#include <cstdint>

#define B_  256
#define T_  1000
#define I_  64
#define H_  128
#define G_  384   // 3*H

typedef unsigned long long u64;

// Scratch for the precomputed input projection x_proj[B][T][3H] (bias folded in).
__device__ float g_xproj[(size_t)B_ * T_ * G_];

// ---- packed fp32x2 helpers (sm_100+) ----------------------------------------
__device__ __forceinline__ u64 fma2(u64 a, u64 b, u64 c) {
    u64 d;
    asm("fma.rn.f32x2 %0, %1, %2, %3;" : "=l"(d) : "l"(a), "l"(b), "l"(c));
    return d;
}
__device__ __forceinline__ float sum2(u64 a) {
    unsigned lo, hi;
    asm("mov.b64 {%0, %1}, %2;" : "=r"(lo), "=r"(hi) : "l"(a));
    return __uint_as_float(lo) + __uint_as_float(hi);
}

// ---------------------------------------------------------------------------
// Kernel A: x_proj[r][g] = sum_i input[r][i] * W_ih[g][i] + b_ih[g]
// ---------------------------------------------------------------------------
__global__ __launch_bounds__(256) void xproj_kernel(
    const float* __restrict__ input,
    const float* __restrict__ W_ih,
    const float* __restrict__ b_ih)
{
    __shared__ float As[64][68];
    __shared__ float Bs[96][66];

    const int tid  = threadIdx.x;
    const size_t row0 = (size_t)blockIdx.x * 64;
    const int col0 = blockIdx.y * 96;

    {
        const float4* a4 = (const float4*)(input + row0 * I_);
        for (int idx = tid; idx < 1024; idx += 256) {
            int r = idx >> 4, c = idx & 15;
            float4 v = a4[r * 16 + c];
            As[r][c * 4 + 0] = v.x;
            As[r][c * 4 + 1] = v.y;
            As[r][c * 4 + 2] = v.z;
            As[r][c * 4 + 3] = v.w;
        }
    }
    for (int idx = tid; idx < 6144; idx += 256) {
        int k = idx & 63, n = idx >> 6;
        Bs[n][k] = W_ih[(size_t)(col0 + n) * I_ + k];
    }
    __syncthreads();

    const int tx = tid & 15;
    const int ty = tid >> 4;

    u64 acc[4][6];
    #pragma unroll
    for (int i = 0; i < 4; ++i)
        #pragma unroll
        for (int jn = 0; jn < 6; ++jn) acc[i][jn] = 0;

    #pragma unroll 4
    for (int kk = 0; kk < 32; ++kk) {
        u64 a[4], b[6];
        #pragma unroll
        for (int i = 0; i < 4; ++i)
            a[i] = *(const u64*)&As[ty * 4 + i][kk * 2];
        #pragma unroll
        for (int jn = 0; jn < 6; ++jn)
            b[jn] = *(const u64*)&Bs[tx + jn * 16][kk * 2];
        #pragma unroll
        for (int i = 0; i < 4; ++i)
            #pragma unroll
            for (int jn = 0; jn < 6; ++jn)
                acc[i][jn] = fma2(a[i], b[jn], acc[i][jn]);
    }

    #pragma unroll
    for (int i = 0; i < 4; ++i) {
        size_t r = row0 + ty * 4 + i;
        #pragma unroll
        for (int jn = 0; jn < 6; ++jn) {
            int c = col0 + tx + jn * 16;
            g_xproj[r * G_ + c] = sum2(acc[i][jn]) + b_ih[c];
        }
    }
}

// ---------------------------------------------------------------------------
// Kernel B: GRU recurrence. 128 CTAs x 512 threads, 2 batches per CTA.
// Thread (q = t>>7, j = t&127) owns k-quarter q of ALL THREE gate rows
// {j, j+128, j+256}, both batches. All 48 W pairs in REGISTERS (96 regs) —
// zero W smem traffic. h interleaved [k2][b]: one broadcast LDS.128 feeds
// 6 fma2. Partials in part[g][b][q][j] (j contiguous -> 1-wf stores/loads).
// Threads t<256 (b = q) finalize the gates for hidden unit j.
// ---------------------------------------------------------------------------
__global__ __launch_bounds__(512, 1) void gru_kernel(
    const float* __restrict__ W_hh,
    const float* __restrict__ b_hh,
    float* __restrict__ out)
{
    __shared__ __align__(16) u64 hint[128];      // [k2][b] interleaved
    __shared__ float part[3][2][4][128];         // [gate][batch][q][j]

    const int t = threadIdx.x;
    const int j = t & 127;
    const int q = t >> 7;                        // k-quarter; batch for t<256
    const int b0 = blockIdx.x * 2;

    const u64* W2u = (const u64*)W_hh;           // W_hh[g][k] as k-pairs

    // All 3 gates' quarter-slices -> registers (48 u64 = 96 regs).
    u64 wreg[48];
    #pragma unroll
    for (int gi = 0; gi < 3; ++gi)
        #pragma unroll
        for (int kk = 0; kk < 16; ++kk)
            wreg[gi * 16 + kk] = W2u[(size_t)(gi * 128 + j) * 64 + q * 16 + kk];

    const float bh0 = b_hh[j];
    const float bh1 = b_hh[j + 128];
    const float bh2 = b_hh[j + 256];

    if (t < 256) ((float*)hint)[t] = 0.f;
    float hreg = 0.f;

    const int qb = q & 1;   // clamp for safe pointer math on q>=2 threads
    const float* xp  = g_xproj + (size_t)(b0 + qb) * T_ * G_ + j;  // used t<256
    float*       stp = out     + (size_t)(b0 + qb) * T_ * H_ + j;

    const ulonglong2* hvec = (const ulonglong2*)hint;  // [k-pair] -> {b0, b1}
    const int hw = (j >> 1) * 4 + q * 2 + (j & 1);     // float slot of h[b=q][j]
    __syncthreads();

    for (int step = 0; step < T_; ++step) {
        // Prefetch this step's input projections (consumed after the barrier).
        float xr = 0.f, xz = 0.f, xn = 0.f;
        if (t < 256) { xr = xp[0]; xz = xp[128]; xn = xp[256]; }

        u64 a00 = 0, a01 = 0, a10 = 0, a11 = 0, a20 = 0, a21 = 0;
        #pragma unroll
        for (int kk = 0; kk < 16; ++kk) {
            ulonglong2 h2 = hvec[q * 16 + kk];   // broadcast: {h_b0, h_b1}
            a00 = fma2(wreg[kk],      h2.x, a00);
            a01 = fma2(wreg[kk],      h2.y, a01);
            a10 = fma2(wreg[16 + kk], h2.x, a10);
            a11 = fma2(wreg[16 + kk], h2.y, a11);
            a20 = fma2(wreg[32 + kk], h2.x, a20);
            a21 = fma2(wreg[32 + kk], h2.y, a21);
        }

        // Quarter partials -> SMEM, j contiguous (1 wavefront per store).
        part[0][0][q][j] = sum2(a00);
        part[0][1][q][j] = sum2(a01);
        part[1][0][q][j] = sum2(a10);
        part[1][1][q][j] = sum2(a11);
        part[2][0][q][j] = sum2(a20);
        part[2][1][q][j] = sum2(a21);
        __syncthreads();

        if (t < 256) {                           // b = q
            const float hr = (part[0][q][0][j] + part[0][q][1][j]) +
                             (part[0][q][2][j] + part[0][q][3][j]) + bh0;
            const float hz = (part[1][q][0][j] + part[1][q][1][j]) +
                             (part[1][q][2][j] + part[1][q][3][j]) + bh1;
            const float hn = (part[2][q][0][j] + part[2][q][1][j]) +
                             (part[2][q][2][j] + part[2][q][3][j]) + bh2;

            const float r = __fdividef(1.f, 1.f + __expf(-(xr + hr)));
            const float z = __fdividef(1.f, 1.f + __expf(-(xz + hz)));
            const float pre = xn + r * hn;
            const float e   = __expf(-2.f * fabsf(pre));
            const float n   = copysignf(__fdividef(1.f - e, 1.f + e), pre);
            hreg = (1.f - z) * n + z * hreg;

            ((float*)hint)[hw] = hreg;
            stp[0] = hreg;
        }
        xp  += G_;
        stp += H_;
        __syncthreads();                         // h visible for next step
    }

    if (t < 256)
        out[(size_t)B_ * T_ * H_ + (size_t)(b0 + q) * H_ + j] = hreg;
}

// ---------------------------------------------------------------------------
// Launcher
// ---------------------------------------------------------------------------
extern "C" void kernel_launch(void* const* d_in, const int* in_sizes, int n_in,
                              void* d_out, int out_size)
{
    const float* input = (const float*)d_in[0];   // [B, T, I]
    const float* W_ih  = (const float*)d_in[1];   // [3H, I]
    const float* W_hh  = (const float*)d_in[2];   // [3H, H]
    const float* b_ih  = (const float*)d_in[3];   // [3H]
    const float* b_hh  = (const float*)d_in[4];   // [3H]
    float* out = (float*)d_out;

    dim3 gridA((B_ * T_) / 64, G_ / 96);   // (4000, 4)
    xproj_kernel<<<gridA, 256>>>(input, W_ih, b_ih);

    gru_kernel<<<B_ / 2, 512>>>(W_hh, b_hh, out);
}

// round 6
// speedup vs baseline: 1.1449x; 1.1449x over previous
#include <cuda_runtime.h>
#include <cstdint>

#define B_  256
#define T_  1000
#define I_  64
#define H_  128
#define G_  384   // 3*H

typedef unsigned long long u64;

// Scratch for the precomputed input projection x_proj[B][T][3H] (bias folded in).
__device__ float g_xproj[(size_t)B_ * T_ * G_];

// ---- packed fp32x2 helpers (sm_100+) ----------------------------------------
__device__ __forceinline__ u64 fma2(u64 a, u64 b, u64 c) {
    u64 d;
    asm("fma.rn.f32x2 %0, %1, %2, %3;" : "=l"(d) : "l"(a), "l"(b), "l"(c));
    return d;
}
__device__ __forceinline__ float sum2(u64 a) {
    unsigned lo, hi;
    asm("mov.b64 {%0, %1}, %2;" : "=r"(lo), "=r"(hi) : "l"(a));
    return __uint_as_float(lo) + __uint_as_float(hi);
}

// ---------------------------------------------------------------------------
// Kernel A: x_proj[r][g] = sum_i input[r][i] * W_ih[g][i] + b_ih[g]
// ---------------------------------------------------------------------------
__global__ __launch_bounds__(256) void xproj_kernel(
    const float* __restrict__ input,
    const float* __restrict__ W_ih,
    const float* __restrict__ b_ih)
{
    __shared__ float As[64][68];
    __shared__ float Bs[96][66];

    const int tid  = threadIdx.x;
    const size_t row0 = (size_t)blockIdx.x * 64;
    const int col0 = blockIdx.y * 96;

    {
        const float4* a4 = (const float4*)(input + row0 * I_);
        for (int idx = tid; idx < 1024; idx += 256) {
            int r = idx >> 4, c = idx & 15;
            float4 v = a4[r * 16 + c];
            As[r][c * 4 + 0] = v.x;
            As[r][c * 4 + 1] = v.y;
            As[r][c * 4 + 2] = v.z;
            As[r][c * 4 + 3] = v.w;
        }
    }
    for (int idx = tid; idx < 6144; idx += 256) {
        int k = idx & 63, n = idx >> 6;
        Bs[n][k] = W_ih[(size_t)(col0 + n) * I_ + k];
    }
    __syncthreads();

    const int tx = tid & 15;
    const int ty = tid >> 4;

    u64 acc[4][6];
    #pragma unroll
    for (int i = 0; i < 4; ++i)
        #pragma unroll
        for (int jn = 0; jn < 6; ++jn) acc[i][jn] = 0;

    #pragma unroll 4
    for (int kk = 0; kk < 32; ++kk) {
        u64 a[4], b[6];
        #pragma unroll
        for (int i = 0; i < 4; ++i)
            a[i] = *(const u64*)&As[ty * 4 + i][kk * 2];
        #pragma unroll
        for (int jn = 0; jn < 6; ++jn)
            b[jn] = *(const u64*)&Bs[tx + jn * 16][kk * 2];
        #pragma unroll
        for (int i = 0; i < 4; ++i)
            #pragma unroll
            for (int jn = 0; jn < 6; ++jn)
                acc[i][jn] = fma2(a[i], b[jn], acc[i][jn]);
    }

    #pragma unroll
    for (int i = 0; i < 4; ++i) {
        size_t r = row0 + ty * 4 + i;
        #pragma unroll
        for (int jn = 0; jn < 6; ++jn) {
            int c = col0 + tx + jn * 16;
            g_xproj[r * G_ + c] = sum2(acc[i][jn]) + b_ih[c];
        }
    }
}

// ---------------------------------------------------------------------------
// Kernel B: GRU recurrence. 128 CTAs x 512 threads, 2 batches per CTA.
// Thread (q = t>>7, j = t&127) owns k-quarter q of gate rows {j, j+128, j+256},
// both batches. W register budget tuned to the 128-reg cap: gates r,z fully in
// regs (32 u64) + first half of gate-n's quarter (8 u64) = 40 u64 (80 regs);
// the other 8 k2 of gate-n come from SMEM (LDS.64, conflict-free).
// h interleaved [k2][b]: one broadcast LDS.128 feeds 6 fma2.
// Partials in part[g][b][q][j] (j contiguous -> 1-wf stores/loads).
// ---------------------------------------------------------------------------
__global__ __launch_bounds__(512, 1) void gru_kernel(
    const float* __restrict__ W_hh,
    const float* __restrict__ b_hh,
    float* __restrict__ out)
{
    __shared__ u64 Wn[32 * 128];                 // [q*8 + m][j], gate-n k2 (x mod 16 >= 8)
    __shared__ __align__(16) u64 hint[128];      // [k2][b] interleaved
    __shared__ float part[3][2][4][128];         // [gate][batch][q][j]

    const int t = threadIdx.x;
    const int j = t & 127;
    const int q = t >> 7;                        // k-quarter; batch for t<256
    const int b0 = blockIdx.x * 2;

    const u64* W2u = (const u64*)W_hh;           // W_hh[g][k] as k-pairs

    // Gates r,z quarter-slices + gate-n first half-quarter -> registers.
    u64 wreg[40];
    #pragma unroll
    for (int gi = 0; gi < 2; ++gi)
        #pragma unroll
        for (int kk = 0; kk < 16; ++kk)
            wreg[gi * 16 + kk] = W2u[(size_t)(gi * 128 + j) * 64 + q * 16 + kk];
    #pragma unroll
    for (int kk = 0; kk < 8; ++kk)
        wreg[32 + kk] = W2u[(size_t)(2 * 128 + j) * 64 + q * 16 + kk];

    // Gate-n second half-quarters -> SMEM: Wn[qq*8 + m][g] for k2 = qq*16+8+m.
    for (int idx = t; idx < 32 * 128; idx += 512) {
        int g   = idx & 127;
        int sid = idx >> 7;                      // qq*8 + m
        int qq  = sid >> 3, m = sid & 7;
        Wn[sid * 128 + g] = W2u[(size_t)(2 * 128 + g) * 64 + qq * 16 + 8 + m];
    }

    const float bh0 = b_hh[j];
    const float bh1 = b_hh[j + 128];
    const float bh2 = b_hh[j + 256];

    if (t < 256) ((float*)hint)[t] = 0.f;
    float hreg = 0.f;

    const int qb = q & 1;   // clamp for safe pointer math on q>=2 threads
    const float* xp  = g_xproj + (size_t)(b0 + qb) * T_ * G_ + j;  // used t<256
    float*       stp = out     + (size_t)(b0 + qb) * T_ * H_ + j;

    const ulonglong2* hvec = (const ulonglong2*)hint;  // [k-pair] -> {b0, b1}
    const u64* wns = Wn + (q * 8) * 128 + j;           // my gate-n smem slice
    const int hw = (j >> 1) * 4 + q * 2 + (j & 1);     // float slot of h[b=q][j]
    __syncthreads();

    for (int step = 0; step < T_; ++step) {
        // Prefetch this step's input projections (consumed after the barrier).
        float xr = 0.f, xz = 0.f, xn = 0.f;
        if (t < 256) { xr = xp[0]; xz = xp[128]; xn = xp[256]; }

        u64 a00 = 0, a01 = 0, a10 = 0, a11 = 0, a20 = 0, a21 = 0;
        // k2 = q*16 + [0,8): gate-n W in registers
        #pragma unroll
        for (int kk = 0; kk < 8; ++kk) {
            ulonglong2 h2 = hvec[q * 16 + kk];   // broadcast
            a00 = fma2(wreg[kk],      h2.x, a00);
            a01 = fma2(wreg[kk],      h2.y, a01);
            a10 = fma2(wreg[16 + kk], h2.x, a10);
            a11 = fma2(wreg[16 + kk], h2.y, a11);
            a20 = fma2(wreg[32 + kk], h2.x, a20);
            a21 = fma2(wreg[32 + kk], h2.y, a21);
        }
        // k2 = q*16 + [8,16): gate-n W from SMEM
        #pragma unroll
        for (int kk = 8; kk < 16; ++kk) {
            ulonglong2 h2 = hvec[q * 16 + kk];   // broadcast
            u64 w2 = wns[(kk - 8) * 128];        // conflict-free LDS.64
            a00 = fma2(wreg[kk],      h2.x, a00);
            a01 = fma2(wreg[kk],      h2.y, a01);
            a10 = fma2(wreg[16 + kk], h2.x, a10);
            a11 = fma2(wreg[16 + kk], h2.y, a11);
            a20 = fma2(w2,            h2.x, a20);
            a21 = fma2(w2,            h2.y, a21);
        }

        // Quarter partials -> SMEM, j contiguous (1 wavefront per store).
        part[0][0][q][j] = sum2(a00);
        part[0][1][q][j] = sum2(a01);
        part[1][0][q][j] = sum2(a10);
        part[1][1][q][j] = sum2(a11);
        part[2][0][q][j] = sum2(a20);
        part[2][1][q][j] = sum2(a21);
        __syncthreads();

        if (t < 256) {                           // b = q
            const float hr = (part[0][q][0][j] + part[0][q][1][j]) +
                             (part[0][q][2][j] + part[0][q][3][j]) + bh0;
            const float hz = (part[1][q][0][j] + part[1][q][1][j]) +
                             (part[1][q][2][j] + part[1][q][3][j]) + bh1;
            const float hn = (part[2][q][0][j] + part[2][q][1][j]) +
                             (part[2][q][2][j] + part[2][q][3][j]) + bh2;

            const float r = __fdividef(1.f, 1.f + __expf(-(xr + hr)));
            const float z = __fdividef(1.f, 1.f + __expf(-(xz + hz)));
            const float pre = xn + r * hn;
            const float e   = __expf(-2.f * fabsf(pre));
            const float n   = copysignf(__fdividef(1.f - e, 1.f + e), pre);
            hreg = (1.f - z) * n + z * hreg;

            ((float*)hint)[hw] = hreg;
            stp[0] = hreg;
        }
        xp  += G_;
        stp += H_;
        __syncthreads();                         // h visible for next step
    }

    if (t < 256)
        out[(size_t)B_ * T_ * H_ + (size_t)(b0 + q) * H_ + j] = hreg;
}

// ---------------------------------------------------------------------------
// Launcher
// ---------------------------------------------------------------------------
extern "C" void kernel_launch(void* const* d_in, const int* in_sizes, int n_in,
                              void* d_out, int out_size)
{
    const float* input = (const float*)d_in[0];   // [B, T, I]
    const float* W_ih  = (const float*)d_in[1];   // [3H, I]
    const float* W_hh  = (const float*)d_in[2];   // [3H, H]
    const float* b_ih  = (const float*)d_in[3];   // [3H]
    const float* b_hh  = (const float*)d_in[4];   // [3H]
    float* out = (float*)d_out;

    dim3 gridA((B_ * T_) / 64, G_ / 96);   // (4000, 4)
    xproj_kernel<<<gridA, 256>>>(input, W_ih, b_ih);

    gru_kernel<<<B_ / 2, 512>>>(W_hh, b_hh, out);
}

// round 7
// speedup vs baseline: 1.2777x; 1.1161x over previous
#include <cuda_runtime.h>
#include <cstdint>

#define B_  256
#define T_  1000
#define I_  64
#define H_  128
#define G_  384   // 3*H

typedef unsigned long long u64;

// Scratch for the precomputed input projection x_proj[B][T][3H] (bias folded in).
__device__ float g_xproj[(size_t)B_ * T_ * G_];

// ---- packed fp32x2 helpers (sm_100+) ----------------------------------------
__device__ __forceinline__ u64 fma2(u64 a, u64 b, u64 c) {
    u64 d;
    asm("fma.rn.f32x2 %0, %1, %2, %3;" : "=l"(d) : "l"(a), "l"(b), "l"(c));
    return d;
}
__device__ __forceinline__ float sum2(u64 a) {
    unsigned lo, hi;
    asm("mov.b64 {%0, %1}, %2;" : "=r"(lo), "=r"(hi) : "l"(a));
    return __uint_as_float(lo) + __uint_as_float(hi);
}

// ---------------------------------------------------------------------------
// Kernel A: x_proj[r][g] = sum_i input[r][i] * W_ih[g][i] + b_ih[g]
// ---------------------------------------------------------------------------
__global__ __launch_bounds__(256) void xproj_kernel(
    const float* __restrict__ input,
    const float* __restrict__ W_ih,
    const float* __restrict__ b_ih)
{
    __shared__ float As[64][68];
    __shared__ float Bs[96][66];

    const int tid  = threadIdx.x;
    const size_t row0 = (size_t)blockIdx.x * 64;
    const int col0 = blockIdx.y * 96;

    {
        const float4* a4 = (const float4*)(input + row0 * I_);
        for (int idx = tid; idx < 1024; idx += 256) {
            int r = idx >> 4, c = idx & 15;
            float4 v = a4[r * 16 + c];
            As[r][c * 4 + 0] = v.x;
            As[r][c * 4 + 1] = v.y;
            As[r][c * 4 + 2] = v.z;
            As[r][c * 4 + 3] = v.w;
        }
    }
    for (int idx = tid; idx < 6144; idx += 256) {
        int k = idx & 63, n = idx >> 6;
        Bs[n][k] = W_ih[(size_t)(col0 + n) * I_ + k];
    }
    __syncthreads();

    const int tx = tid & 15;
    const int ty = tid >> 4;

    u64 acc[4][6];
    #pragma unroll
    for (int i = 0; i < 4; ++i)
        #pragma unroll
        for (int jn = 0; jn < 6; ++jn) acc[i][jn] = 0;

    #pragma unroll 4
    for (int kk = 0; kk < 32; ++kk) {
        u64 a[4], b[6];
        #pragma unroll
        for (int i = 0; i < 4; ++i)
            a[i] = *(const u64*)&As[ty * 4 + i][kk * 2];
        #pragma unroll
        for (int jn = 0; jn < 6; ++jn)
            b[jn] = *(const u64*)&Bs[tx + jn * 16][kk * 2];
        #pragma unroll
        for (int i = 0; i < 4; ++i)
            #pragma unroll
            for (int jn = 0; jn < 6; ++jn)
                acc[i][jn] = fma2(a[i], b[jn], acc[i][jn]);
    }

    #pragma unroll
    for (int i = 0; i < 4; ++i) {
        size_t r = row0 + ty * 4 + i;
        #pragma unroll
        for (int jn = 0; jn < 6; ++jn) {
            int c = col0 + tx + jn * 16;
            g_xproj[r * G_ + c] = sum2(acc[i][jn]) + b_ih[c];
        }
    }
}

// ---------------------------------------------------------------------------
// Kernel B: GRU recurrence. 128 CTAs x 512 threads, 2 batches per CTA.
// Thread (q = t>>7, j = t&127) owns k-quarter q of gate rows {j, j+128, j+256},
// both batches. Gates r,z in REGISTERS (32 u64 = 64 regs — the empirically
// feasible RF budget); gate n streamed from SMEM as PAIRED ulonglong2 loads
// (8 LDS.128/thread/step, conflict-free). h interleaved [k2][b]: one
// broadcast LDS.128 feeds 6 fma2. Partials in part[g][b][q][j] (j contiguous
// -> 1-wf stores/loads). Threads t<256 (b = q) finalize hidden unit j.
// ---------------------------------------------------------------------------
__global__ __launch_bounds__(512, 1) void gru_kernel(
    const float* __restrict__ W_hh,
    const float* __restrict__ b_hh,
    float* __restrict__ out)
{
    extern __shared__ __align__(16) char smraw[];
    ulonglong2* Wnp = (ulonglong2*)smraw;            // [32 sid][128 j] = 65536 B
    u64*   hint = (u64*)(smraw + 65536);             // [64 k2][2 b]   = 1024 B
    float* part = (float*)(smraw + 66560);           // [3][2][4][128] = 12288 B

    const int t = threadIdx.x;
    const int j = t & 127;
    const int q = t >> 7;                            // k-quarter; batch for t<256
    const int b0 = blockIdx.x * 2;

    const u64* W2u = (const u64*)W_hh;               // W_hh[g][k] as k-pairs

    // Gates r,z quarter-slices -> registers (32 u64 = 64 regs).
    u64 wreg[32];
    #pragma unroll
    for (int gi = 0; gi < 2; ++gi)
        #pragma unroll
        for (int kk = 0; kk < 16; ++kk)
            wreg[gi * 16 + kk] = W2u[(size_t)(gi * 128 + j) * 64 + q * 16 + kk];

    // Gate-n -> SMEM as paired k2: Wnp[qq*8 + m][g] = {k2=qq*16+2m, +2m+1}.
    for (int idx = t; idx < 32 * 128; idx += 512) {
        int g   = idx & 127;
        int sid = idx >> 7;                          // qq*8 + m
        int qq  = sid >> 3, m = sid & 7;
        const u64* src = &W2u[(size_t)(2 * 128 + g) * 64 + qq * 16 + 2 * m];
        ulonglong2 v; v.x = src[0]; v.y = src[1];
        Wnp[sid * 128 + g] = v;
    }

    const float bh0 = b_hh[j];
    const float bh1 = b_hh[j + 128];
    const float bh2 = b_hh[j + 256];

    if (t < 256) ((float*)hint)[t] = 0.f;
    float hreg = 0.f;

    const int qb = q & 1;   // clamp for safe pointer math on q>=2 threads
    const float* xp  = g_xproj + (size_t)(b0 + qb) * T_ * G_ + j;  // used t<256
    float*       stp = out     + (size_t)(b0 + qb) * T_ * H_ + j;

    const ulonglong2* hvec = (const ulonglong2*)hint;  // [k-pair] -> {b0, b1}
    const ulonglong2* wnp  = Wnp + (q * 8) * 128 + j;  // my gate-n smem slice
    const int hw = (j >> 1) * 4 + q * 2 + (j & 1);     // float slot of h[b=q][j]
    __syncthreads();

    for (int step = 0; step < T_; ++step) {
        // Prefetch this step's input projections (consumed after the barrier).
        float xr = 0.f, xz = 0.f, xn = 0.f;
        if (t < 256) { xr = xp[0]; xz = xp[128]; xn = xp[256]; }

        u64 a00 = 0, a01 = 0, a10 = 0, a11 = 0, a20 = 0, a21 = 0;
        #pragma unroll
        for (int m = 0; m < 8; ++m) {
            ulonglong2 h2a = hvec[q * 16 + 2 * m];       // broadcast
            ulonglong2 h2b = hvec[q * 16 + 2 * m + 1];   // broadcast
            ulonglong2 w2  = wnp[m * 128];               // LDS.128, conflict-free
            a00 = fma2(wreg[2 * m],          h2a.x, a00);
            a01 = fma2(wreg[2 * m],          h2a.y, a01);
            a10 = fma2(wreg[16 + 2 * m],     h2a.x, a10);
            a11 = fma2(wreg[16 + 2 * m],     h2a.y, a11);
            a20 = fma2(w2.x,                 h2a.x, a20);
            a21 = fma2(w2.x,                 h2a.y, a21);
            a00 = fma2(wreg[2 * m + 1],      h2b.x, a00);
            a01 = fma2(wreg[2 * m + 1],      h2b.y, a01);
            a10 = fma2(wreg[16 + 2 * m + 1], h2b.x, a10);
            a11 = fma2(wreg[16 + 2 * m + 1], h2b.y, a11);
            a20 = fma2(w2.y,                 h2b.x, a20);
            a21 = fma2(w2.y,                 h2b.y, a21);
        }

        // Quarter partials -> SMEM, j contiguous (1 wavefront per store).
        part[((0 * 2 + 0) * 4 + q) * 128 + j] = sum2(a00);
        part[((0 * 2 + 1) * 4 + q) * 128 + j] = sum2(a01);
        part[((1 * 2 + 0) * 4 + q) * 128 + j] = sum2(a10);
        part[((1 * 2 + 1) * 4 + q) * 128 + j] = sum2(a11);
        part[((2 * 2 + 0) * 4 + q) * 128 + j] = sum2(a20);
        part[((2 * 2 + 1) * 4 + q) * 128 + j] = sum2(a21);
        __syncthreads();

        if (t < 256) {                           // b = q
            const float* pr = &part[(0 * 2 + q) * 4 * 128 + j];
            const float* pz = &part[(1 * 2 + q) * 4 * 128 + j];
            const float* pn = &part[(2 * 2 + q) * 4 * 128 + j];
            const float hr = (pr[0] + pr[128]) + (pr[256] + pr[384]) + bh0;
            const float hz = (pz[0] + pz[128]) + (pz[256] + pz[384]) + bh1;
            const float hn = (pn[0] + pn[128]) + (pn[256] + pn[384]) + bh2;

            const float r = __fdividef(1.f, 1.f + __expf(-(xr + hr)));
            const float z = __fdividef(1.f, 1.f + __expf(-(xz + hz)));
            const float pre = xn + r * hn;
            const float e   = __expf(-2.f * fabsf(pre));
            const float n   = copysignf(__fdividef(1.f - e, 1.f + e), pre);
            hreg = (1.f - z) * n + z * hreg;

            ((float*)hint)[hw] = hreg;
            stp[0] = hreg;
        }
        xp  += G_;
        stp += H_;
        __syncthreads();                         // h visible for next step
    }

    if (t < 256)
        out[(size_t)B_ * T_ * H_ + (size_t)(b0 + q) * H_ + j] = hreg;
}

// ---------------------------------------------------------------------------
// Launcher
// ---------------------------------------------------------------------------
extern "C" void kernel_launch(void* const* d_in, const int* in_sizes, int n_in,
                              void* d_out, int out_size)
{
    const float* input = (const float*)d_in[0];   // [B, T, I]
    const float* W_ih  = (const float*)d_in[1];   // [3H, I]
    const float* W_hh  = (const float*)d_in[2];   // [3H, H]
    const float* b_ih  = (const float*)d_in[3];   // [3H]
    const float* b_hh  = (const float*)d_in[4];   // [3H]
    float* out = (float*)d_out;

    const int smem_bytes = 65536 + 1024 + 12288;  // 78848
    cudaFuncSetAttribute(gru_kernel, cudaFuncAttributeMaxDynamicSharedMemorySize,
                         smem_bytes);

    dim3 gridA((B_ * T_) / 64, G_ / 96);   // (4000, 4)
    xproj_kernel<<<gridA, 256>>>(input, W_ih, b_ih);

    gru_kernel<<<B_ / 2, 512, smem_bytes>>>(W_hh, b_hh, out);
}

// round 8
// speedup vs baseline: 1.3011x; 1.0183x over previous
#include <cuda_runtime.h>
#include <cstdint>

#define B_  256
#define T_  1000
#define I_  64
#define H_  128
#define G_  384   // 3*H

typedef unsigned long long u64;

// Scratch for the precomputed input projection x_proj[B][T][3H] (bias folded in).
__device__ float g_xproj[(size_t)B_ * T_ * G_];

// ---- packed fp32x2 helpers (sm_100+) ----------------------------------------
__device__ __forceinline__ u64 fma2(u64 a, u64 b, u64 c) {
    u64 d;
    asm("fma.rn.f32x2 %0, %1, %2, %3;" : "=l"(d) : "l"(a), "l"(b), "l"(c));
    return d;
}
__device__ __forceinline__ float sum2(u64 a) {
    unsigned lo, hi;
    asm("mov.b64 {%0, %1}, %2;" : "=r"(lo), "=r"(hi) : "l"(a));
    return __uint_as_float(lo) + __uint_as_float(hi);
}
// MUFU.TANH — single-op tanh (max rel err ~2^-11)
__device__ __forceinline__ float tanha(float x) {
    float y;
    asm("tanh.approx.f32 %0, %1;" : "=f"(y) : "f"(x));
    return y;
}

// ---------------------------------------------------------------------------
// Kernel A: x_proj[r][g] = sum_i input[r][i] * W_ih[g][i] + b_ih[g]
// 1024 threads, 64 rows x 384 cols per CTA (full W_ih tile, input read once).
// Thread (ty = t>>7, tx = t&127): 8 rows (ty*8+i) x 3 cols (tx + jn*128).
// ty is warp-uniform -> A loads are broadcasts. Stores: 32 consecutive cols
// per warp -> perfect 128B STG segments. Operands as paired-k ulonglong2.
// ---------------------------------------------------------------------------
__global__ __launch_bounds__(1024) void xproj_kernel(
    const float* __restrict__ input,
    const float* __restrict__ W_ih,
    const float* __restrict__ b_ih)
{
    extern __shared__ __align__(16) u64 xsm[];
    u64* As = xsm;                 // [64][34] k-pairs, padded
    u64* Bs = xsm + 64 * 34;       // [384][34] k-pairs, padded

    const int t = threadIdx.x;
    const size_t row0 = (size_t)blockIdx.x * 64;

    // Load input tile (64 x 64 fp32 = 2048 u64), coalesced.
    {
        const u64* inu = (const u64*)(input + row0 * I_);
        #pragma unroll
        for (int p = 0; p < 2; ++p) {
            int idx = t + p * 1024;
            int r = idx >> 5, kk = idx & 31;
            As[r * 34 + kk] = inu[idx];
        }
    }
    // Load full W_ih (384 x 64 fp32 = 12288 u64), coalesced.
    {
        const u64* wu = (const u64*)W_ih;
        #pragma unroll
        for (int p = 0; p < 12; ++p) {
            int idx = t + p * 1024;
            int n = idx >> 5, kk = idx & 31;
            Bs[n * 34 + kk] = wu[idx];
        }
    }
    __syncthreads();

    const int tx = t & 127;
    const int ty = t >> 7;         // warp-uniform

    u64 acc[8][3];
    #pragma unroll
    for (int i = 0; i < 8; ++i)
        #pragma unroll
        for (int jn = 0; jn < 3; ++jn) acc[i][jn] = 0;

    #pragma unroll
    for (int kk2 = 0; kk2 < 16; ++kk2) {       // two k-pairs per iter
        ulonglong2 a2[8], b2[3];
        #pragma unroll
        for (int i = 0; i < 8; ++i)
            a2[i] = *(const ulonglong2*)&As[(ty * 8 + i) * 34 + 2 * kk2];
        #pragma unroll
        for (int jn = 0; jn < 3; ++jn)
            b2[jn] = *(const ulonglong2*)&Bs[(tx + jn * 128) * 34 + 2 * kk2];
        #pragma unroll
        for (int i = 0; i < 8; ++i)
            #pragma unroll
            for (int jn = 0; jn < 3; ++jn) {
                acc[i][jn] = fma2(a2[i].x, b2[jn].x, acc[i][jn]);
                acc[i][jn] = fma2(a2[i].y, b2[jn].y, acc[i][jn]);
            }
    }

    float bias[3];
    #pragma unroll
    for (int jn = 0; jn < 3; ++jn) bias[jn] = b_ih[tx + jn * 128];

    #pragma unroll
    for (int i = 0; i < 8; ++i) {
        float* orow = g_xproj + (row0 + ty * 8 + i) * G_;
        #pragma unroll
        for (int jn = 0; jn < 3; ++jn)
            orow[tx + jn * 128] = sum2(acc[i][jn]) + bias[jn];
    }
}

// ---------------------------------------------------------------------------
// Kernel B: GRU recurrence. 128 CTAs x 512 threads, 2 batches per CTA.
// Thread (q = t>>7, j = t&127) owns k-quarter q of gate rows {j, j+128, j+256},
// both batches. Gates r,z in REGISTERS (32 u64); gate n streamed from SMEM as
// paired ulonglong2 with a 1-deep software-pipelined prefetch. h interleaved
// [k2][b]: one broadcast LDS.128 feeds 6 fma2. Partials in part[g][b][q][j]
// (j contiguous -> 1-wf stores/loads). Gate nonlinearities via MUFU.TANH.
// ---------------------------------------------------------------------------
__global__ __launch_bounds__(512, 1) void gru_kernel(
    const float* __restrict__ W_hh,
    const float* __restrict__ b_hh,
    float* __restrict__ out)
{
    extern __shared__ __align__(16) char smraw[];
    ulonglong2* Wnp = (ulonglong2*)smraw;            // [32 sid][128 j] = 65536 B
    u64*   hint = (u64*)(smraw + 65536);             // [64 k2][2 b]   = 1024 B
    float* part = (float*)(smraw + 66560);           // [3][2][4][128] = 12288 B

    const int t = threadIdx.x;
    const int j = t & 127;
    const int q = t >> 7;                            // k-quarter; batch for t<256
    const int b0 = blockIdx.x * 2;

    const u64* W2u = (const u64*)W_hh;               // W_hh[g][k] as k-pairs

    // Gates r,z quarter-slices -> registers (32 u64 = 64 regs).
    u64 wreg[32];
    #pragma unroll
    for (int gi = 0; gi < 2; ++gi)
        #pragma unroll
        for (int kk = 0; kk < 16; ++kk)
            wreg[gi * 16 + kk] = W2u[(size_t)(gi * 128 + j) * 64 + q * 16 + kk];

    // Gate-n -> SMEM as paired k2: Wnp[qq*8 + m][g] = {k2=qq*16+2m, +2m+1}.
    for (int idx = t; idx < 32 * 128; idx += 512) {
        int g   = idx & 127;
        int sid = idx >> 7;                          // qq*8 + m
        int qq  = sid >> 3, m = sid & 7;
        const u64* src = &W2u[(size_t)(2 * 128 + g) * 64 + qq * 16 + 2 * m];
        ulonglong2 v; v.x = src[0]; v.y = src[1];
        Wnp[sid * 128 + g] = v;
    }

    const float bh0 = b_hh[j];
    const float bh1 = b_hh[j + 128];
    const float bh2 = b_hh[j + 256];

    if (t < 256) ((float*)hint)[t] = 0.f;
    float hreg = 0.f;

    const int qb = q & 1;   // clamp for safe pointer math on q>=2 threads
    const float* xp  = g_xproj + (size_t)(b0 + qb) * T_ * G_ + j;  // used t<256
    float*       stp = out     + (size_t)(b0 + qb) * T_ * H_ + j;

    const ulonglong2* hvec = (const ulonglong2*)hint;  // [k-pair] -> {b0, b1}
    const ulonglong2* wnp  = Wnp + (q * 8) * 128 + j;  // my gate-n smem slice
    const int hw = (j >> 1) * 4 + q * 2 + (j & 1);     // float slot of h[b=q][j]
    __syncthreads();

    for (int step = 0; step < T_; ++step) {
        // Prefetch this step's input projections (consumed after the barrier).
        float xr = 0.f, xz = 0.f, xn = 0.f;
        if (t < 256) { xr = xp[0]; xz = xp[128]; xn = xp[256]; }

        u64 a00 = 0, a01 = 0, a10 = 0, a11 = 0, a20 = 0, a21 = 0;
        ulonglong2 w2 = wnp[0];                      // software-pipelined W_n
        #pragma unroll
        for (int m = 0; m < 8; ++m) {
            ulonglong2 h2a = hvec[q * 16 + 2 * m];       // broadcast
            ulonglong2 h2b = hvec[q * 16 + 2 * m + 1];   // broadcast
            ulonglong2 w2c = w2;
            if (m < 7) w2 = wnp[(m + 1) * 128];          // prefetch next
            a00 = fma2(wreg[2 * m],          h2a.x, a00);
            a01 = fma2(wreg[2 * m],          h2a.y, a01);
            a10 = fma2(wreg[16 + 2 * m],     h2a.x, a10);
            a11 = fma2(wreg[16 + 2 * m],     h2a.y, a11);
            a20 = fma2(w2c.x,                h2a.x, a20);
            a21 = fma2(w2c.x,                h2a.y, a21);
            a00 = fma2(wreg[2 * m + 1],      h2b.x, a00);
            a01 = fma2(wreg[2 * m + 1],      h2b.y, a01);
            a10 = fma2(wreg[16 + 2 * m + 1], h2b.x, a10);
            a11 = fma2(wreg[16 + 2 * m + 1], h2b.y, a11);
            a20 = fma2(w2c.y,                h2b.x, a20);
            a21 = fma2(w2c.y,                h2b.y, a21);
        }

        // Quarter partials -> SMEM, j contiguous (1 wavefront per store).
        part[((0 * 2 + 0) * 4 + q) * 128 + j] = sum2(a00);
        part[((0 * 2 + 1) * 4 + q) * 128 + j] = sum2(a01);
        part[((1 * 2 + 0) * 4 + q) * 128 + j] = sum2(a10);
        part[((1 * 2 + 1) * 4 + q) * 128 + j] = sum2(a11);
        part[((2 * 2 + 0) * 4 + q) * 128 + j] = sum2(a20);
        part[((2 * 2 + 1) * 4 + q) * 128 + j] = sum2(a21);
        __syncthreads();

        if (t < 256) {                           // b = q
            const float* pr = &part[(0 * 2 + q) * 4 * 128 + j];
            const float* pz = &part[(1 * 2 + q) * 4 * 128 + j];
            const float* pn = &part[(2 * 2 + q) * 4 * 128 + j];
            const float hr = (pr[0] + pr[128]) + (pr[256] + pr[384]) + bh0;
            const float hz = (pz[0] + pz[128]) + (pz[256] + pz[384]) + bh1;
            const float hn = (pn[0] + pn[128]) + (pn[256] + pn[384]) + bh2;

            // sigmoid(x) = 0.5 + 0.5*tanh(0.5x); all via MUFU.TANH.
            const float r = 0.5f + 0.5f * tanha(0.5f * (xr + hr));
            const float z = 0.5f + 0.5f * tanha(0.5f * (xz + hz));
            const float n = tanha(xn + r * hn);
            hreg = n + z * (hreg - n);           // (1-z)n + z*h

            ((float*)hint)[hw] = hreg;
            stp[0] = hreg;
        }
        xp  += G_;
        stp += H_;
        __syncthreads();                         // h visible for next step
    }

    if (t < 256)
        out[(size_t)B_ * T_ * H_ + (size_t)(b0 + q) * H_ + j] = hreg;
}

// ---------------------------------------------------------------------------
// Launcher
// ---------------------------------------------------------------------------
extern "C" void kernel_launch(void* const* d_in, const int* in_sizes, int n_in,
                              void* d_out, int out_size)
{
    const float* input = (const float*)d_in[0];   // [B, T, I]
    const float* W_ih  = (const float*)d_in[1];   // [3H, I]
    const float* W_hh  = (const float*)d_in[2];   // [3H, H]
    const float* b_ih  = (const float*)d_in[3];   // [3H]
    const float* b_hh  = (const float*)d_in[4];   // [3H]
    float* out = (float*)d_out;

    const int xp_smem = (64 * 34 + 384 * 34) * 8;   // 121856 B
    cudaFuncSetAttribute(xproj_kernel, cudaFuncAttributeMaxDynamicSharedMemorySize,
                         xp_smem);
    const int gru_smem = 65536 + 1024 + 12288;      // 78848 B
    cudaFuncSetAttribute(gru_kernel, cudaFuncAttributeMaxDynamicSharedMemorySize,
                         gru_smem);

    xproj_kernel<<<(B_ * T_) / 64, 1024, xp_smem>>>(input, W_ih, b_ih);
    gru_kernel<<<B_ / 2, 512, gru_smem>>>(W_hh, b_hh, out);
}